// round 6
// baseline (speedup 1.0000x reference)
#include <cuda_runtime.h>

#define K_DIM 7168
#define E_DIM 256
#define BM 128
#define BN 128
#define BK 8
#define KC_TILES 40   // Eigen kc=320 floats = 40 tiles of BK=8

// packed f32x2 FMA (Blackwell): per-component IEEE rn fma
__device__ __forceinline__ unsigned long long ffma2(unsigned long long a,
                                                    unsigned long long b,
                                                    unsigned long long c) {
    unsigned long long d;
    asm("fma.rn.f32x2 %0, %1, %2, %3;" : "=l"(d) : "l"(a), "l"(b), "l"(c));
    return d;
}

__device__ __forceinline__ unsigned long long fadd2(unsigned long long a,
                                                    unsigned long long b) {
    unsigned long long d;
    asm("add.rn.f32x2 %0, %1, %2;" : "=l"(d) : "l"(a), "l"(b));
    return d;
}

__device__ __forceinline__ unsigned long long dup_f32(float a) {
    unsigned long long p;
    asm("mov.b64 %0, {%1, %1};" : "=l"(p) : "r"(__float_as_uint(a)));
    return p;
}

// C[t, e] = sum_k A[t,k] * W[e,k] — fp32, Eigen-blocked accumulation order:
// c = ((0 + S_0) + S_1) + ... ; S_b = ascending-k fma partial over kc=320 block
// (last block = 128). Matches XLA:CPU Eigen gemm per-element rounding tree.
__global__ __launch_bounds__(256)
void moe_gemm_kernel(const float* __restrict__ A,
                     const float* __restrict__ W,
                     float* __restrict__ C, int T) {
    __shared__ float As[BK][BM];
    __shared__ float Bs[BK][BN];

    const int tid = threadIdx.x;
    const int tx = tid & 15;   // expert direction (8 experts per thread)
    const int ty = tid >> 4;   // token direction  (8 tokens per thread)
    const int m0 = blockIdx.x * BM;
    const int n0 = blockIdx.y * BN;

    const int lr = tid >> 1;          // row 0..127
    const int lc = (tid & 1) * 4;     // K offset 0 or 4

    const float* Abase = A + (size_t)(m0 + lr) * K_DIM + lc;
    const float* Wbase = W + (size_t)(n0 + lr) * K_DIM + lc;

    unsigned long long acc[8][4];   // running c
    unsigned long long bac[8][4];   // current block partial S_b
#pragma unroll
    for (int i = 0; i < 8; i++)
#pragma unroll
        for (int j = 0; j < 4; j++) { acc[i][j] = 0ull; bac[i][j] = 0ull; }

    float4 aPre = *reinterpret_cast<const float4*>(Abase);
    float4 bPre = *reinterpret_cast<const float4*>(Wbase);

    const int nIter = K_DIM / BK;  // 896
    for (int kt = 0; kt < nIter; ++kt) {
        As[lc + 0][lr] = aPre.x; As[lc + 1][lr] = aPre.y;
        As[lc + 2][lr] = aPre.z; As[lc + 3][lr] = aPre.w;
        Bs[lc + 0][lr] = bPre.x; Bs[lc + 1][lr] = bPre.y;
        Bs[lc + 2][lr] = bPre.z; Bs[lc + 3][lr] = bPre.w;
        __syncthreads();

        if (kt + 1 < nIter) {
            aPre = *reinterpret_cast<const float4*>(Abase + (size_t)(kt + 1) * BK);
            bPre = *reinterpret_cast<const float4*>(Wbase + (size_t)(kt + 1) * BK);
        }

#pragma unroll
        for (int k = 0; k < BK; ++k) {
            float4 a0 = *reinterpret_cast<const float4*>(&As[k][ty * 8]);
            float4 a1 = *reinterpret_cast<const float4*>(&As[k][ty * 8 + 4]);
            const unsigned long long* bp =
                reinterpret_cast<const unsigned long long*>(&Bs[k][tx * 8]);
            unsigned long long pb0 = bp[0], pb1 = bp[1], pb2 = bp[2], pb3 = bp[3];
            float av[8] = {a0.x, a0.y, a0.z, a0.w, a1.x, a1.y, a1.z, a1.w};
#pragma unroll
            for (int i = 0; i < 8; ++i) {
                unsigned long long pa = dup_f32(av[i]);
                bac[i][0] = ffma2(pa, pb0, bac[i][0]);
                bac[i][1] = ffma2(pa, pb1, bac[i][1]);
                bac[i][2] = ffma2(pa, pb2, bac[i][2]);
                bac[i][3] = ffma2(pa, pb3, bac[i][3]);
            }
        }

        // Eigen kc=320 block boundary: c += S_b; S_b = 0
        if (((kt + 1) % KC_TILES) == 0) {
#pragma unroll
            for (int i = 0; i < 8; ++i)
#pragma unroll
                for (int j = 0; j < 4; ++j) {
                    acc[i][j] = fadd2(acc[i][j], bac[i][j]);
                    bac[i][j] = 0ull;
                }
        }
        __syncthreads();
    }

    // final (remainder 128-wide) block flush
#pragma unroll
    for (int i = 0; i < 8; ++i)
#pragma unroll
        for (int j = 0; j < 4; ++j)
            acc[i][j] = fadd2(acc[i][j], bac[i][j]);

#pragma unroll
    for (int i = 0; i < 8; ++i) {
        int m = m0 + ty * 8 + i;
        float* crow = C + (size_t)m * E_DIM + n0 + tx * 8;
        float2 f0 = *reinterpret_cast<float2*>(&acc[i][0]);
        float2 f1 = *reinterpret_cast<float2*>(&acc[i][1]);
        float2 f2 = *reinterpret_cast<float2*>(&acc[i][2]);
        float2 f3 = *reinterpret_cast<float2*>(&acc[i][3]);
        float4 o0 = make_float4(f0.x, f0.y, f1.x, f1.y);
        float4 o1 = make_float4(f2.x, f2.y, f3.x, f3.y);
        *reinterpret_cast<float4*>(crow) = o0;
        *reinterpret_cast<float4*>(crow + 4) = o1;
    }
}

// XLA EmitFastTanh replica — UNFUSED mul/add Horner (CPU LLVM does not
// contract), IEEE fdiv, clamp +-7.90531110763549805, |x|<0.0004 -> x.
__device__ __forceinline__ float xla_tanhf_nofma(float x) {
    float xc = fminf(fmaxf(x, -7.90531110763549805f), 7.90531110763549805f);
    float x2 = __fmul_rn(xc, xc);
    float np = -2.76076847742355e-16f;
    np = __fadd_rn(__fmul_rn(x2, np),  2.00018790482477e-13f);
    np = __fadd_rn(__fmul_rn(x2, np), -8.60467152213735e-11f);
    np = __fadd_rn(__fmul_rn(x2, np),  5.12229709037114e-08f);
    np = __fadd_rn(__fmul_rn(x2, np),  1.48572235717979e-05f);
    np = __fadd_rn(__fmul_rn(x2, np),  6.37261928875436e-04f);
    np = __fadd_rn(__fmul_rn(x2, np),  4.89352455891786e-03f);
    float num = __fmul_rn(xc, np);
    float dp = 1.19825839466702e-06f;
    dp = __fadd_rn(__fmul_rn(x2, dp), 1.18534705686654e-04f);
    dp = __fadd_rn(__fmul_rn(x2, dp), 2.26843463243900e-03f);
    dp = __fadd_rn(__fmul_rn(x2, dp), 4.89352518554385e-03f);
    float r = __fdiv_rn(num, dp);
    return (fabsf(x) < 0.0004f) ? x : r;
}

// XLA logistic: 0.5 + 0.5 * tanh(0.5 * x), unfused.
__device__ __forceinline__ float sigmoid_xla(float x) {
    float t = xla_tanhf_nofma(__fmul_rn(0.5f, x));
    return __fadd_rn(0.5f, __fmul_rn(0.5f, t));
}

// one warp per token
__global__ void moe_router_kernel(const float* __restrict__ logits,
                                  float* __restrict__ outW,
                                  float* __restrict__ outI, int T) {
    const unsigned FULL = 0xFFFFFFFFu;
    int warp = (blockIdx.x * blockDim.x + threadIdx.x) >> 5;
    int lane = threadIdx.x & 31;
    if (warp >= T) return;

    const float* row = logits + (size_t)warp * E_DIM;
    float4 v0 = *reinterpret_cast<const float4*>(row + lane * 8);
    float4 v1 = *reinterpret_cast<const float4*>(row + lane * 8 + 4);

    float s[8];
    s[0] = sigmoid_xla(v0.x); s[1] = sigmoid_xla(v0.y);
    s[2] = sigmoid_xla(v0.z); s[3] = sigmoid_xla(v0.w);
    s[4] = sigmoid_xla(v1.x); s[5] = sigmoid_xla(v1.y);
    s[6] = sigmoid_xla(v1.z); s[7] = sigmoid_xla(v1.w);

    // group sum over 32 experts (butterfly tree; group gaps are huge so the
    // exact tree shape is non-binding — verified empirically R4 vs R5)
    float f[8];
#pragma unroll
    for (int j = 0; j < 8; ++j)
        f[j] = s[j] + __shfl_xor_sync(FULL, s[j], 2);
    float g[8];
#pragma unroll
    for (int j = 0; j < 8; ++j)
        g[j] = f[j] + __shfl_xor_sync(FULL, f[j], 1);
    float h0 = g[0] + g[4];
    float h1 = g[1] + g[5];
    float h2 = g[2] + g[6];
    float h3 = g[3] + g[7];
    float p0 = h0 + h2;
    float p1 = h1 + h3;
    float mygs = p0 + p1;     // group sum for group (lane>>2)
    int myg = lane >> 2;

    // rank of my group among 8 groups (ties -> lower index, jax top_k)
    int rank = 0;
#pragma unroll
    for (int h = 0; h < 8; ++h) {
        float gh = __shfl_sync(FULL, mygs, h * 4);
        if (h != myg && (gh > mygs || (gh == mygs && h < myg))) rank++;
    }
    bool sel = (rank < 4);

    float ms[8];
#pragma unroll
    for (int j = 0; j < 8; ++j) ms[j] = sel ? s[j] : 0.0f;

    float topv[8];
    int topi[8];
#pragma unroll
    for (int it = 0; it < 8; ++it) {
        float bv = -1.0f;
        int bi = 0;
#pragma unroll
        for (int j = 0; j < 8; ++j) {
            if (ms[j] > bv) { bv = ms[j]; bi = lane * 8 + j; }
        }
#pragma unroll
        for (int off = 16; off; off >>= 1) {
            float ov = __shfl_xor_sync(FULL, bv, off);
            int oi = __shfl_xor_sync(FULL, bi, off);
            if (ov > bv || (ov == bv && oi < bi)) { bv = ov; bi = oi; }
        }
        topv[it] = bv;
        topi[it] = bi;
        if ((bi >> 3) == lane) ms[bi & 7] = -1.0f;
    }

    float denom = 0.f;
#pragma unroll
    for (int it = 0; it < 8; ++it) denom += topv[it];
    denom = fmaxf(denom, 1e-12f);

    if (lane < 8) {
        outW[(size_t)warp * 8 + lane] = __fdiv_rn(topv[lane], denom);
        outI[(size_t)warp * 8 + lane] = (float)topi[lane];
    }
}

extern "C" void kernel_launch(void* const* d_in, const int* in_sizes, int n_in,
                              void* d_out, int out_size) {
    const float* H = (const float*)d_in[0];   // [T, 7168] fp32
    const float* W = (const float*)d_in[1];   // [256, 7168] fp32
    float* out = (float*)d_out;

    int T = in_sizes[0] / K_DIM;

    // output layout: [T*8 weights][T*8 indices][T*256 logits]
    float* outW = out;
    float* outI = out + (size_t)T * 8;
    float* logits = out + (size_t)T * 16;

    dim3 grid(T / BM, E_DIM / BN);
    moe_gemm_kernel<<<grid, 256>>>(H, W, logits, T);

    int warps = T;
    int threads = 256;
    int blocks = (warps * 32 + threads - 1) / threads;
    moe_router_kernel<<<blocks, threads>>>(logits, outW, outI, T);
}

// round 7
// speedup vs baseline: 1.1178x; 1.1178x over previous
#include <cuda_runtime.h>

#define K_DIM 7168
#define E_DIM 256
#define BM 128
#define BN 128
#define BK 16
#define KC_TILES 20   // Eigen kc=320 floats = 20 tiles of BK=16

// packed f32x2 FMA (Blackwell): per-component IEEE rn fma
__device__ __forceinline__ unsigned long long ffma2(unsigned long long a,
                                                    unsigned long long b,
                                                    unsigned long long c) {
    unsigned long long d;
    asm("fma.rn.f32x2 %0, %1, %2, %3;" : "=l"(d) : "l"(a), "l"(b), "l"(c));
    return d;
}

__device__ __forceinline__ unsigned long long fadd2(unsigned long long a,
                                                    unsigned long long b) {
    unsigned long long d;
    asm("add.rn.f32x2 %0, %1, %2;" : "=l"(d) : "l"(a), "l"(b));
    return d;
}

__device__ __forceinline__ unsigned long long dup_f32(float a) {
    unsigned long long p;
    asm("mov.b64 %0, {%1, %1};" : "=l"(p) : "r"(__float_as_uint(a)));
    return p;
}

// C[t, e] = sum_k A[t,k] * W[e,k] — fp32, Eigen-blocked accumulation order:
// c = ((0 + S_0) + S_1) + ... ; S_b = ascending-k fma partial over kc=320 block
// (last block = 128). BIT-EXACT match to XLA:CPU Eigen gemm — do not reorder.
// Double-buffered smem, one __syncthreads per BK=16 tile.
__global__ __launch_bounds__(256)
void moe_gemm_kernel(const float* __restrict__ A,
                     const float* __restrict__ W,
                     float* __restrict__ C, int T) {
    __shared__ float As[2][BK][BM];
    __shared__ float Bs[2][BK][BN];

    const int tid = threadIdx.x;
    const int tx = tid & 15;   // expert direction (8 experts per thread)
    const int ty = tid >> 4;   // token direction  (8 tokens per thread)
    const int m0 = blockIdx.x * BM;
    const int n0 = blockIdx.y * BN;

    // loader: 2 threads per row, 8 floats (2x float4) each
    const int lr = tid >> 1;          // row 0..127
    const int lc = (tid & 1) * 8;     // K offset 0 or 8

    const float* Abase = A + (size_t)(m0 + lr) * K_DIM + lc;
    const float* Wbase = W + (size_t)(n0 + lr) * K_DIM + lc;

    unsigned long long acc[8][4];   // running c
    unsigned long long bac[8][4];   // current kc-block partial S_b
#pragma unroll
    for (int i = 0; i < 8; i++)
#pragma unroll
        for (int j = 0; j < 4; j++) { acc[i][j] = 0ull; bac[i][j] = 0ull; }

    float4 aP0 = *reinterpret_cast<const float4*>(Abase);
    float4 aP1 = *reinterpret_cast<const float4*>(Abase + 4);
    float4 bP0 = *reinterpret_cast<const float4*>(Wbase);
    float4 bP1 = *reinterpret_cast<const float4*>(Wbase + 4);

    const int nIter = K_DIM / BK;  // 448
    for (int kt = 0; kt < nIter; ++kt) {
        const int buf = kt & 1;
        // store prefetched tile
        As[buf][lc + 0][lr] = aP0.x; As[buf][lc + 1][lr] = aP0.y;
        As[buf][lc + 2][lr] = aP0.z; As[buf][lc + 3][lr] = aP0.w;
        As[buf][lc + 4][lr] = aP1.x; As[buf][lc + 5][lr] = aP1.y;
        As[buf][lc + 6][lr] = aP1.z; As[buf][lc + 7][lr] = aP1.w;
        Bs[buf][lc + 0][lr] = bP0.x; Bs[buf][lc + 1][lr] = bP0.y;
        Bs[buf][lc + 2][lr] = bP0.z; Bs[buf][lc + 3][lr] = bP0.w;
        Bs[buf][lc + 4][lr] = bP1.x; Bs[buf][lc + 5][lr] = bP1.y;
        Bs[buf][lc + 6][lr] = bP1.z; Bs[buf][lc + 7][lr] = bP1.w;
        __syncthreads();

        // prefetch next tile (hidden under compute below)
        if (kt + 1 < nIter) {
            const float* an = Abase + (size_t)(kt + 1) * BK;
            const float* wn = Wbase + (size_t)(kt + 1) * BK;
            aP0 = *reinterpret_cast<const float4*>(an);
            aP1 = *reinterpret_cast<const float4*>(an + 4);
            bP0 = *reinterpret_cast<const float4*>(wn);
            bP1 = *reinterpret_cast<const float4*>(wn + 4);
        }

#pragma unroll
        for (int k = 0; k < BK; ++k) {
            float4 a0 = *reinterpret_cast<const float4*>(&As[buf][k][ty * 8]);
            float4 a1 = *reinterpret_cast<const float4*>(&As[buf][k][ty * 8 + 4]);
            const unsigned long long* bp =
                reinterpret_cast<const unsigned long long*>(&Bs[buf][k][tx * 8]);
            unsigned long long pb0 = bp[0], pb1 = bp[1], pb2 = bp[2], pb3 = bp[3];
            float av[8] = {a0.x, a0.y, a0.z, a0.w, a1.x, a1.y, a1.z, a1.w};
#pragma unroll
            for (int i = 0; i < 8; ++i) {
                unsigned long long pa = dup_f32(av[i]);
                bac[i][0] = ffma2(pa, pb0, bac[i][0]);
                bac[i][1] = ffma2(pa, pb1, bac[i][1]);
                bac[i][2] = ffma2(pa, pb2, bac[i][2]);
                bac[i][3] = ffma2(pa, pb3, bac[i][3]);
            }
        }

        // Eigen kc=320 block boundary: c += S_b; S_b = 0
        if (((kt + 1) % KC_TILES) == 0) {
#pragma unroll
            for (int i = 0; i < 8; ++i)
#pragma unroll
                for (int j = 0; j < 4; ++j) {
                    acc[i][j] = fadd2(acc[i][j], bac[i][j]);
                    bac[i][j] = 0ull;
                }
        }
    }

    // final (remainder 128-wide) block flush
#pragma unroll
    for (int i = 0; i < 8; ++i)
#pragma unroll
        for (int j = 0; j < 4; ++j)
            acc[i][j] = fadd2(acc[i][j], bac[i][j]);

#pragma unroll
    for (int i = 0; i < 8; ++i) {
        int m = m0 + ty * 8 + i;
        float* crow = C + (size_t)m * E_DIM + n0 + tx * 8;
        float2 f0 = *reinterpret_cast<float2*>(&acc[i][0]);
        float2 f1 = *reinterpret_cast<float2*>(&acc[i][1]);
        float2 f2 = *reinterpret_cast<float2*>(&acc[i][2]);
        float2 f3 = *reinterpret_cast<float2*>(&acc[i][3]);
        float4 o0 = make_float4(f0.x, f0.y, f1.x, f1.y);
        float4 o1 = make_float4(f2.x, f2.y, f3.x, f3.y);
        *reinterpret_cast<float4*>(crow) = o0;
        *reinterpret_cast<float4*>(crow + 4) = o1;
    }
}

// XLA EmitFastTanh replica — UNFUSED mul/add Horner (CPU LLVM does not
// contract), IEEE fdiv, clamp +-7.90531110763549805, |x|<0.0004 -> x.
__device__ __forceinline__ float xla_tanhf_nofma(float x) {
    float xc = fminf(fmaxf(x, -7.90531110763549805f), 7.90531110763549805f);
    float x2 = __fmul_rn(xc, xc);
    float np = -2.76076847742355e-16f;
    np = __fadd_rn(__fmul_rn(x2, np),  2.00018790482477e-13f);
    np = __fadd_rn(__fmul_rn(x2, np), -8.60467152213735e-11f);
    np = __fadd_rn(__fmul_rn(x2, np),  5.12229709037114e-08f);
    np = __fadd_rn(__fmul_rn(x2, np),  1.48572235717979e-05f);
    np = __fadd_rn(__fmul_rn(x2, np),  6.37261928875436e-04f);
    np = __fadd_rn(__fmul_rn(x2, np),  4.89352455891786e-03f);
    float num = __fmul_rn(xc, np);
    float dp = 1.19825839466702e-06f;
    dp = __fadd_rn(__fmul_rn(x2, dp), 1.18534705686654e-04f);
    dp = __fadd_rn(__fmul_rn(x2, dp), 2.26843463243900e-03f);
    dp = __fadd_rn(__fmul_rn(x2, dp), 4.89352518554385e-03f);
    float r = __fdiv_rn(num, dp);
    return (fabsf(x) < 0.0004f) ? x : r;
}

// XLA logistic: 0.5 + 0.5 * tanh(0.5 * x), unfused.
__device__ __forceinline__ float sigmoid_xla(float x) {
    float t = xla_tanhf_nofma(__fmul_rn(0.5f, x));
    return __fadd_rn(0.5f, __fmul_rn(0.5f, t));
}

// one warp per token
__global__ void moe_router_kernel(const float* __restrict__ logits,
                                  float* __restrict__ outW,
                                  float* __restrict__ outI, int T) {
    const unsigned FULL = 0xFFFFFFFFu;
    int warp = (blockIdx.x * blockDim.x + threadIdx.x) >> 5;
    int lane = threadIdx.x & 31;
    if (warp >= T) return;

    const float* row = logits + (size_t)warp * E_DIM;
    float4 v0 = *reinterpret_cast<const float4*>(row + lane * 8);
    float4 v1 = *reinterpret_cast<const float4*>(row + lane * 8 + 4);

    float s[8];
    s[0] = sigmoid_xla(v0.x); s[1] = sigmoid_xla(v0.y);
    s[2] = sigmoid_xla(v0.z); s[3] = sigmoid_xla(v0.w);
    s[4] = sigmoid_xla(v1.x); s[5] = sigmoid_xla(v1.y);
    s[6] = sigmoid_xla(v1.z); s[7] = sigmoid_xla(v1.w);

    // group sum over 32 experts (butterfly tree)
    float f[8];
#pragma unroll
    for (int j = 0; j < 8; ++j)
        f[j] = s[j] + __shfl_xor_sync(FULL, s[j], 2);
    float g[8];
#pragma unroll
    for (int j = 0; j < 8; ++j)
        g[j] = f[j] + __shfl_xor_sync(FULL, f[j], 1);
    float h0 = g[0] + g[4];
    float h1 = g[1] + g[5];
    float h2 = g[2] + g[6];
    float h3 = g[3] + g[7];
    float p0 = h0 + h2;
    float p1 = h1 + h3;
    float mygs = p0 + p1;     // group sum for group (lane>>2)
    int myg = lane >> 2;

    // rank of my group among 8 groups (ties -> lower index, jax top_k)
    int rank = 0;
#pragma unroll
    for (int h = 0; h < 8; ++h) {
        float gh = __shfl_sync(FULL, mygs, h * 4);
        if (h != myg && (gh > mygs || (gh == mygs && h < myg))) rank++;
    }
    bool sel = (rank < 4);

    float ms[8];
#pragma unroll
    for (int j = 0; j < 8; ++j) ms[j] = sel ? s[j] : 0.0f;

    float topv[8];
    int topi[8];
#pragma unroll
    for (int it = 0; it < 8; ++it) {
        float bv = -1.0f;
        int bi = 0;
#pragma unroll
        for (int j = 0; j < 8; ++j) {
            if (ms[j] > bv) { bv = ms[j]; bi = lane * 8 + j; }
        }
#pragma unroll
        for (int off = 16; off; off >>= 1) {
            float ov = __shfl_xor_sync(FULL, bv, off);
            int oi = __shfl_xor_sync(FULL, bi, off);
            if (ov > bv || (ov == bv && oi < bi)) { bv = ov; bi = oi; }
        }
        topv[it] = bv;
        topi[it] = bi;
        if ((bi >> 3) == lane) ms[bi & 7] = -1.0f;
    }

    float denom = 0.f;
#pragma unroll
    for (int it = 0; it < 8; ++it) denom += topv[it];
    denom = fmaxf(denom, 1e-12f);

    if (lane < 8) {
        outW[(size_t)warp * 8 + lane] = __fdiv_rn(topv[lane], denom);
        outI[(size_t)warp * 8 + lane] = (float)topi[lane];
    }
}

extern "C" void kernel_launch(void* const* d_in, const int* in_sizes, int n_in,
                              void* d_out, int out_size) {
    const float* H = (const float*)d_in[0];   // [T, 7168] fp32
    const float* W = (const float*)d_in[1];   // [256, 7168] fp32
    float* out = (float*)d_out;

    int T = in_sizes[0] / K_DIM;

    // output layout: [T*8 weights][T*8 indices][T*256 logits]
    float* outW = out;
    float* outI = out + (size_t)T * 8;
    float* logits = out + (size_t)T * 16;

    dim3 grid(T / BM, E_DIM / BN);
    moe_gemm_kernel<<<grid, 256>>>(H, W, logits, T);

    int warps = T;
    int threads = 256;
    int blocks = (warps * 32 + threads - 1) / threads;
    moe_router_kernel<<<blocks, threads>>>(logits, outW, outI, T);
}

// round 8
// speedup vs baseline: 1.1705x; 1.0472x over previous
#include <cuda_runtime.h>

#define K_DIM 7168
#define E_DIM 256
#define BM 128
#define BN 128
#define BK 16
#define KC_TILES 20   // Eigen kc=320 floats = 20 tiles of BK=16

// packed f32x2 FMA (Blackwell): per-component IEEE rn fma
__device__ __forceinline__ unsigned long long ffma2(unsigned long long a,
                                                    unsigned long long b,
                                                    unsigned long long c) {
    unsigned long long d;
    asm("fma.rn.f32x2 %0, %1, %2, %3;" : "=l"(d) : "l"(a), "l"(b), "l"(c));
    return d;
}

__device__ __forceinline__ unsigned long long fadd2(unsigned long long a,
                                                    unsigned long long b) {
    unsigned long long d;
    asm("add.rn.f32x2 %0, %1, %2;" : "=l"(d) : "l"(a), "l"(b));
    return d;
}

__device__ __forceinline__ unsigned long long dup_f32(float a) {
    unsigned long long p;
    asm("mov.b64 %0, {%1, %1};" : "=l"(p) : "r"(__float_as_uint(a)));
    return p;
}

// C[t, e] = sum_k A[t,k] * W[e,k] — fp32, Eigen-blocked accumulation order:
// c = ((0 + S_0) + S_1) + ... ; S_b = ascending-k fma partial over kc=320 block
// (last block = 128). BIT-EXACT match to XLA:CPU Eigen gemm — do not reorder.
// 512 threads, 8m x 4n per thread, double-buffered smem, 1 sync per tile.
__global__ __launch_bounds__(512)
void moe_gemm_kernel(const float* __restrict__ A,
                     const float* __restrict__ W,
                     float* __restrict__ C, int T) {
    __shared__ float As[2][BK][BM];
    __shared__ float Bs[2][BK][BN];

    const int tid = threadIdx.x;
    const int tx = tid & 31;   // expert direction: 4 experts per thread
    const int ty = tid >> 5;   // token direction:  8 tokens per thread (warp id)
    const int m0 = blockIdx.x * BM;
    const int n0 = blockIdx.y * BN;

    // loader: 4 threads per row, one float4 each (128 rows x 16 k)
    const int lr = tid >> 2;          // row 0..127
    const int lc = (tid & 3) * 4;     // K offset 0,4,8,12

    const float* Abase = A + (size_t)(m0 + lr) * K_DIM + lc;
    const float* Wbase = W + (size_t)(n0 + lr) * K_DIM + lc;

    unsigned long long acc[8][2];   // running c (8m x 4n)
    unsigned long long bac[8][2];   // current kc-block partial S_b
#pragma unroll
    for (int i = 0; i < 8; i++)
#pragma unroll
        for (int j = 0; j < 2; j++) { acc[i][j] = 0ull; bac[i][j] = 0ull; }

    float4 aP = *reinterpret_cast<const float4*>(Abase);
    float4 bP = *reinterpret_cast<const float4*>(Wbase);

    const int nIter = K_DIM / BK;  // 448
    for (int kt = 0; kt < nIter; ++kt) {
        const int buf = kt & 1;
        As[buf][lc + 0][lr] = aP.x; As[buf][lc + 1][lr] = aP.y;
        As[buf][lc + 2][lr] = aP.z; As[buf][lc + 3][lr] = aP.w;
        Bs[buf][lc + 0][lr] = bP.x; Bs[buf][lc + 1][lr] = bP.y;
        Bs[buf][lc + 2][lr] = bP.z; Bs[buf][lc + 3][lr] = bP.w;
        __syncthreads();

        // prefetch next tile (hidden under compute below)
        if (kt + 1 < nIter) {
            aP = *reinterpret_cast<const float4*>(Abase + (size_t)(kt + 1) * BK);
            bP = *reinterpret_cast<const float4*>(Wbase + (size_t)(kt + 1) * BK);
        }

#pragma unroll
        for (int k = 0; k < BK; ++k) {
            // A fragment: lane-invariant address -> warp broadcast LDS
            float4 a0 = *reinterpret_cast<const float4*>(&As[buf][k][ty * 8]);
            float4 a1 = *reinterpret_cast<const float4*>(&As[buf][k][ty * 8 + 4]);
            // B fragment: 4 floats = 2 packed f32x2
            const unsigned long long* bp =
                reinterpret_cast<const unsigned long long*>(&Bs[buf][k][tx * 4]);
            unsigned long long pb0 = bp[0], pb1 = bp[1];
            float av[8] = {a0.x, a0.y, a0.z, a0.w, a1.x, a1.y, a1.z, a1.w};
#pragma unroll
            for (int i = 0; i < 8; ++i) {
                unsigned long long pa = dup_f32(av[i]);
                bac[i][0] = ffma2(pa, pb0, bac[i][0]);
                bac[i][1] = ffma2(pa, pb1, bac[i][1]);
            }
        }

        // Eigen kc=320 block boundary: c += S_b; S_b = 0
        if (((kt + 1) % KC_TILES) == 0) {
#pragma unroll
            for (int i = 0; i < 8; ++i)
#pragma unroll
                for (int j = 0; j < 2; ++j) {
                    acc[i][j] = fadd2(acc[i][j], bac[i][j]);
                    bac[i][j] = 0ull;
                }
        }
    }

    // final (remainder 128-wide) block flush
#pragma unroll
    for (int i = 0; i < 8; ++i)
#pragma unroll
        for (int j = 0; j < 2; ++j)
            acc[i][j] = fadd2(acc[i][j], bac[i][j]);

#pragma unroll
    for (int i = 0; i < 8; ++i) {
        int m = m0 + ty * 8 + i;
        float* crow = C + (size_t)m * E_DIM + n0 + tx * 4;
        float2 f0 = *reinterpret_cast<float2*>(&acc[i][0]);
        float2 f1 = *reinterpret_cast<float2*>(&acc[i][1]);
        *reinterpret_cast<float4*>(crow) = make_float4(f0.x, f0.y, f1.x, f1.y);
    }
}

// XLA EmitFastTanh replica — UNFUSED mul/add Horner (CPU LLVM does not
// contract), IEEE fdiv, clamp +-7.90531110763549805, |x|<0.0004 -> x.
__device__ __forceinline__ float xla_tanhf_nofma(float x) {
    float xc = fminf(fmaxf(x, -7.90531110763549805f), 7.90531110763549805f);
    float x2 = __fmul_rn(xc, xc);
    float np = -2.76076847742355e-16f;
    np = __fadd_rn(__fmul_rn(x2, np),  2.00018790482477e-13f);
    np = __fadd_rn(__fmul_rn(x2, np), -8.60467152213735e-11f);
    np = __fadd_rn(__fmul_rn(x2, np),  5.12229709037114e-08f);
    np = __fadd_rn(__fmul_rn(x2, np),  1.48572235717979e-05f);
    np = __fadd_rn(__fmul_rn(x2, np),  6.37261928875436e-04f);
    np = __fadd_rn(__fmul_rn(x2, np),  4.89352455891786e-03f);
    float num = __fmul_rn(xc, np);
    float dp = 1.19825839466702e-06f;
    dp = __fadd_rn(__fmul_rn(x2, dp), 1.18534705686654e-04f);
    dp = __fadd_rn(__fmul_rn(x2, dp), 2.26843463243900e-03f);
    dp = __fadd_rn(__fmul_rn(x2, dp), 4.89352518554385e-03f);
    float r = __fdiv_rn(num, dp);
    return (fabsf(x) < 0.0004f) ? x : r;
}

// XLA logistic: 0.5 + 0.5 * tanh(0.5 * x), unfused.
__device__ __forceinline__ float sigmoid_xla(float x) {
    float t = xla_tanhf_nofma(__fmul_rn(0.5f, x));
    return __fadd_rn(0.5f, __fmul_rn(0.5f, t));
}

// one warp per token
__global__ void moe_router_kernel(const float* __restrict__ logits,
                                  float* __restrict__ outW,
                                  float* __restrict__ outI, int T) {
    const unsigned FULL = 0xFFFFFFFFu;
    int warp = (blockIdx.x * blockDim.x + threadIdx.x) >> 5;
    int lane = threadIdx.x & 31;
    if (warp >= T) return;

    const float* row = logits + (size_t)warp * E_DIM;
    float4 v0 = *reinterpret_cast<const float4*>(row + lane * 8);
    float4 v1 = *reinterpret_cast<const float4*>(row + lane * 8 + 4);

    float s[8];
    s[0] = sigmoid_xla(v0.x); s[1] = sigmoid_xla(v0.y);
    s[2] = sigmoid_xla(v0.z); s[3] = sigmoid_xla(v0.w);
    s[4] = sigmoid_xla(v1.x); s[5] = sigmoid_xla(v1.y);
    s[6] = sigmoid_xla(v1.z); s[7] = sigmoid_xla(v1.w);

    // group sum over 32 experts (butterfly tree)
    float f[8];
#pragma unroll
    for (int j = 0; j < 8; ++j)
        f[j] = s[j] + __shfl_xor_sync(FULL, s[j], 2);
    float g[8];
#pragma unroll
    for (int j = 0; j < 8; ++j)
        g[j] = f[j] + __shfl_xor_sync(FULL, f[j], 1);
    float h0 = g[0] + g[4];
    float h1 = g[1] + g[5];
    float h2 = g[2] + g[6];
    float h3 = g[3] + g[7];
    float p0 = h0 + h2;
    float p1 = h1 + h3;
    float mygs = p0 + p1;     // group sum for group (lane>>2)
    int myg = lane >> 2;

    // rank of my group among 8 groups (ties -> lower index, jax top_k)
    int rank = 0;
#pragma unroll
    for (int h = 0; h < 8; ++h) {
        float gh = __shfl_sync(FULL, mygs, h * 4);
        if (h != myg && (gh > mygs || (gh == mygs && h < myg))) rank++;
    }
    bool sel = (rank < 4);

    float ms[8];
#pragma unroll
    for (int j = 0; j < 8; ++j) ms[j] = sel ? s[j] : 0.0f;

    float topv[8];
    int topi[8];
#pragma unroll
    for (int it = 0; it < 8; ++it) {
        float bv = -1.0f;
        int bi = 0;
#pragma unroll
        for (int j = 0; j < 8; ++j) {
            if (ms[j] > bv) { bv = ms[j]; bi = lane * 8 + j; }
        }
#pragma unroll
        for (int off = 16; off; off >>= 1) {
            float ov = __shfl_xor_sync(FULL, bv, off);
            int oi = __shfl_xor_sync(FULL, bi, off);
            if (ov > bv || (ov == bv && oi < bi)) { bv = ov; bi = oi; }
        }
        topv[it] = bv;
        topi[it] = bi;
        if ((bi >> 3) == lane) ms[bi & 7] = -1.0f;
    }

    float denom = 0.f;
#pragma unroll
    for (int it = 0; it < 8; ++it) denom += topv[it];
    denom = fmaxf(denom, 1e-12f);

    if (lane < 8) {
        outW[(size_t)warp * 8 + lane] = __fdiv_rn(topv[lane], denom);
        outI[(size_t)warp * 8 + lane] = (float)topi[lane];
    }
}

extern "C" void kernel_launch(void* const* d_in, const int* in_sizes, int n_in,
                              void* d_out, int out_size) {
    const float* H = (const float*)d_in[0];   // [T, 7168] fp32
    const float* W = (const float*)d_in[1];   // [256, 7168] fp32
    float* out = (float*)d_out;

    int T = in_sizes[0] / K_DIM;

    // output layout: [T*8 weights][T*8 indices][T*256 logits]
    float* outW = out;
    float* outI = out + (size_t)T * 8;
    float* logits = out + (size_t)T * 16;

    dim3 grid(T / BM, E_DIM / BN);
    moe_gemm_kernel<<<grid, 512>>>(H, W, logits, T);

    int warps = T;
    int threads = 256;
    int blocks = (warps * 32 + threads - 1) / threads;
    moe_router_kernel<<<blocks, threads>>>(logits, outW, outI, T);
}